// round 14
// baseline (speedup 1.0000x reference)
#include <cuda_runtime.h>
#include <cuda_fp16.h>
#include <math.h>

#define BB    128
#define TT    1024
#define IND   256
#define HH    512
#define NH    1024          // 2*H
#define FC1N  2048
#define OUTN  128
#define EPSF  1e-5f

#define M_BIG (TT * BB)
#define NCTA  128
#define GNUM  16            // CTAs per sync group (bt x direction)

// fp16 recurrence smem: 4 arrays of [32 rows][264 words]
#define AWST  264
#define RNN_SMEM (4 * 32 * AWST * 4)    // 135,168 bytes

// ---- tf32 split (gemm_tc; R7/R8-verified) ----
__device__ __forceinline__ void tf32_split(float x, unsigned &hi, unsigned &lo) {
    unsigned h;
    asm("cvt.rna.tf32.f32 %0, %1;" : "=r"(h) : "f"(x));
    float rem = x - __uint_as_float(h);
    unsigned l;
    asm("cvt.rna.tf32.f32 %0, %1;" : "=r"(l) : "f"(rem));
    hi = h; lo = l;
}

__device__ __forceinline__ void mma8(float* d, const unsigned* a, const unsigned* b) {
    asm volatile(
        "mma.sync.aligned.m16n8k8.row.col.f32.tf32.tf32.f32 "
        "{%0,%1,%2,%3}, {%4,%5,%6,%7}, {%8,%9}, {%0,%1,%2,%3};"
        : "+f"(d[0]), "+f"(d[1]), "+f"(d[2]), "+f"(d[3])
        : "r"(a[0]), "r"(a[1]), "r"(a[2]), "r"(a[3]), "r"(b[0]), "r"(b[1]));
}

__device__ __forceinline__ void mma16(float* d, const unsigned* a, const unsigned* b) {
    asm volatile(
        "mma.sync.aligned.m16n8k16.row.col.f32.f16.f16.f32 "
        "{%0,%1,%2,%3}, {%4,%5,%6,%7}, {%8,%9}, {%0,%1,%2,%3};"
        : "+f"(d[0]), "+f"(d[1]), "+f"(d[2]), "+f"(d[3])
        : "r"(a[0]), "r"(a[1]), "r"(a[2]), "r"(a[3]), "r"(b[0]), "r"(b[1]));
}

__device__ __forceinline__ void f16split2(float x0, float x1, unsigned &hw, unsigned &lw) {
    __half a0 = __float2half_rn(x0);
    __half a1 = __float2half_rn(x1);
    float r0 = (x0 - __half2float(a0)) * 2048.f;
    float r1 = (x1 - __half2float(a1)) * 2048.f;
    __half b0 = __float2half_rn(r0);
    __half b1 = __float2half_rn(r1);
    hw = ((unsigned)__half_as_ushort(a1) << 16) | (unsigned)__half_as_ushort(a0);
    lw = ((unsigned)__half_as_ushort(b1) << 16) | (unsigned)__half_as_ushort(b0);
}

__device__ __forceinline__ void cp16(unsigned smem_addr, const void* gptr) {
    asm volatile("cp.async.cg.shared.global [%0], [%1], 16;"
                 :: "r"(smem_addr), "l"(gptr));
}

__device__ __forceinline__ int ld_acq(const int* p) {
    int v;
    asm volatile("ld.acquire.gpu.global.s32 %0, [%1];" : "=r"(v) : "l"(p) : "memory");
    return v;
}
__device__ __forceinline__ void red_rel(int* p) {
    asm volatile("red.release.gpu.global.add.s32 [%0], %1;" :: "l"(p), "r"(1) : "memory");
}

// ---------------- device scratch ----------------
__device__ float    g_P[TT * BB * NH];
__device__ float    g_H0buf[TT * BB * NH];
__device__ unsigned g_h016h[BB * NH / 2];
__device__ unsigned g_h016l[BB * NH / 2];
__device__ unsigned g_h116h[BB * NH / 2];
__device__ unsigned g_h116l[BB * NH / 2];
__device__ unsigned g_HhA[BB * NH / 2];     // layer-0 fp16 ping-pong
__device__ unsigned g_HhB[BB * NH / 2];
__device__ unsigned g_HlA[BB * NH / 2];
__device__ unsigned g_HlB[BB * NH / 2];
__device__ unsigned g_Hh1A[BB * NH / 2];    // layer-1 fp16 ping-pong (separate: layers may overlap)
__device__ unsigned g_Hh1B[BB * NH / 2];
__device__ unsigned g_Hl1A[BB * NH / 2];
__device__ unsigned g_Hl1B[BB * NH / 2];
__device__ float    g_h1a[BB * NH];
__device__ float    g_h1b[BB * NH];
__device__ float    g_bias0[NH];
__device__ float    g_bias1[NH];
__device__ float    g_y1[BB * NH];
__device__ float    g_z[BB * FC1N];
__device__ int      g_ctr0[TT * 8];
__device__ int      g_ctr1[TT * 8];
__device__ int      g_pf0[TT];              // P0 tile-ready counters (8 per t)
__device__ int      g_pf1[TT];              // P1 tile-ready counters (8 per t)
__device__ int      g_hdone[TT];            // H0[t] complete counters (128 per t)

// ---------------- setup ----------------
__global__ void setup_kernel(const float* __restrict__ h0,
                             const float* __restrict__ bih0, const float* __restrict__ bhh0,
                             const float* __restrict__ bih1, const float* __restrict__ bhh1)
{
    int i0 = blockIdx.x * blockDim.x + threadIdx.x;
    if (i0 < NH) {
        g_bias0[i0] = bih0[i0] + bhh0[i0];
        g_bias1[i0] = bih1[i0] + bhh1[i0];
    }
    if (i0 < TT * 8) { g_ctr0[i0] = 0; g_ctr1[i0] = 0; }
    if (i0 < TT) { g_pf0[i0] = 0; g_pf1[i0] = 0; g_hdone[i0] = 0; }
    int stride = gridDim.x * blockDim.x;
    for (int wi = i0; wi < BB * (NH / 2); wi += stride) {
        int b  = wi >> 9;
        int kp = wi & 511;
        int d  = kp >> 8;
        int j0 = (kp * 2) & (HH - 1);
        float v0a = h0[(size_t)(d * BB + b) * HH + j0];
        float v0b = h0[(size_t)(d * BB + b) * HH + j0 + 1];
        float v1a = h0[(size_t)((2 + d) * BB + b) * HH + j0];
        float v1b = h0[(size_t)((2 + d) * BB + b) * HH + j0 + 1];
        unsigned hw, lw;
        f16split2(v0a, v0b, hw, lw);
        g_h016h[wi] = hw; g_h016l[wi] = lw;
        f16split2(v1a, v1b, hw, lw);
        g_h116h[wi] = hw; g_h116l[wi] = lw;
    }
}

// ---------------- tensor-core GEMM (tf32x3), per-t flag protocol --------------------
// blockIdx.y == timestep t (CTA m-tile of 128 rows = one timestep since BB = 128).
// cons: wait cons[t] >= consTgt before reading A. prod: signal prod[t] += 1 when done.
#define SK 20
template<int AMODE>
__global__ void __launch_bounds__(256) gemm_tc(
    const float* __restrict__ A, const float* __restrict__ W,
    const float* __restrict__ bias, float* __restrict__ C,
    int M, int N, int K,
    const int* __restrict__ cons, int consTgt, int* __restrict__ prod)
{
    cudaTriggerProgrammaticLaunchCompletion();

    __shared__ unsigned sAh[128][SK];
    __shared__ unsigned sAl[128][SK];
    __shared__ unsigned sWh[128][SK];
    __shared__ unsigned sWl[128][SK];

    const int m0   = blockIdx.y * 128;
    const int n0   = blockIdx.x * 128;
    const int tid  = threadIdx.x;
    const int lane = tid & 31;
    const int warp = tid >> 5;
    const int wm   = (warp & 1) * 64;
    const int wn   = (warp >> 1) * 32;
    const int r    = lane >> 2;
    const int q    = lane & 3;

    const int srow = tid >> 1;
    const int scg  = (tid & 1) * 8;

    if (cons) {
        if (tid == 0) {
            const int* cp = &cons[blockIdx.y];
            while (ld_acq(cp) < consTgt) __nanosleep(64);
        }
        __syncthreads();
    }

    float acc[4][4][4];
#pragma unroll
    for (int i = 0; i < 4; i++)
#pragma unroll
        for (int j = 0; j < 4; j++)
#pragma unroll
            for (int c = 0; c < 4; c++) acc[i][j][c] = 0.f;

    const float* arow;
    {
        int m = m0 + srow;
        if (AMODE == 1) arow = A + ((size_t)((m & (BB - 1)) * TT + (m >> 7))) * K;
        else            arow = A + (size_t)m * K;
    }
    const float* wrow = W + (size_t)(n0 + srow) * K;

    for (int k0 = 0; k0 < K; k0 += 16) {
        float4 av0 = *(const float4*)&arow[k0 + scg];
        float4 av1 = *(const float4*)&arow[k0 + scg + 4];
        float4 wv0 = *(const float4*)&wrow[k0 + scg];
        float4 wv1 = *(const float4*)&wrow[k0 + scg + 4];
        const float* af = (const float*)&av0;
#pragma unroll
        for (int j = 0; j < 4; j++) tf32_split(af[j], sAh[srow][scg + j], sAl[srow][scg + j]);
        af = (const float*)&av1;
#pragma unroll
        for (int j = 0; j < 4; j++) tf32_split(af[j], sAh[srow][scg + 4 + j], sAl[srow][scg + 4 + j]);
        const float* wf = (const float*)&wv0;
#pragma unroll
        for (int j = 0; j < 4; j++) tf32_split(wf[j], sWh[srow][scg + j], sWl[srow][scg + j]);
        wf = (const float*)&wv1;
#pragma unroll
        for (int j = 0; j < 4; j++) tf32_split(wf[j], sWh[srow][scg + 4 + j], sWl[srow][scg + 4 + j]);
        __syncthreads();

#pragma unroll
        for (int kk = 0; kk < 16; kk += 8) {
            unsigned bh[4][2], bl[4][2];
#pragma unroll
            for (int nt = 0; nt < 4; nt++) {
                int nn = wn + nt * 8 + r;
                bh[nt][0] = sWh[nn][kk + q];
                bh[nt][1] = sWh[nn][kk + q + 4];
                bl[nt][0] = sWl[nn][kk + q];
                bl[nt][1] = sWl[nn][kk + q + 4];
            }
#pragma unroll
            for (int mt = 0; mt < 4; mt++) {
                int mm = wm + mt * 16 + r;
                unsigned ah[4], al[4];
                ah[0] = sAh[mm][kk + q];     ah[1] = sAh[mm + 8][kk + q];
                ah[2] = sAh[mm][kk + q + 4]; ah[3] = sAh[mm + 8][kk + q + 4];
                al[0] = sAl[mm][kk + q];     al[1] = sAl[mm + 8][kk + q];
                al[2] = sAl[mm][kk + q + 4]; al[3] = sAl[mm + 8][kk + q + 4];
#pragma unroll
                for (int nt = 0; nt < 4; nt++) {
                    mma8(acc[mt][nt], ah, bh[nt]);
                    mma8(acc[mt][nt], ah, bl[nt]);
                    mma8(acc[mt][nt], al, bh[nt]);
                }
            }
        }
        __syncthreads();
    }

#pragma unroll
    for (int mt = 0; mt < 4; mt++) {
#pragma unroll
        for (int nt = 0; nt < 4; nt++) {
            int n  = n0 + wn + nt * 8 + q * 2;
            int ml = m0 + wm + mt * 16 + r;
            float bx = bias[n], by = bias[n + 1];
            float2 o0 = make_float2(acc[mt][nt][0] + bx, acc[mt][nt][1] + by);
            float2 o1 = make_float2(acc[mt][nt][2] + bx, acc[mt][nt][3] + by);
            *(float2*)&C[(size_t)ml * N + n]       = o0;
            *(float2*)&C[(size_t)(ml + 8) * N + n] = o1;
        }
    }

    __syncthreads();
    if (prod && tid == 0) red_rel(&prod[blockIdx.y]);
}

// ---------------- persistent recurrence: fp16x3 + per-t P-ready gating --------------
template<int LAYER0>
__global__ void __launch_bounds__(128, 1) rnn_mma(
    const float* __restrict__ P, const float* __restrict__ WhhG,
    const unsigned* __restrict__ h0H16, const unsigned* __restrict__ h0L16,
    float* __restrict__ Hbuf, float* __restrict__ f32A, float* __restrict__ f32B,
    unsigned* __restrict__ HhA, unsigned* __restrict__ HhB,
    unsigned* __restrict__ HlA, unsigned* __restrict__ HlB,
    int* __restrict__ ctr, const int* __restrict__ pReady, int* __restrict__ hDone)
{
    cudaTriggerProgrammaticLaunchCompletion();

    extern __shared__ unsigned usm[];
    unsigned* uWh = usm;                    // [32][AWST]
    unsigned* uWl = uWh + 32 * AWST;
    unsigned* uAh = uWl + 32 * AWST;
    unsigned* uAl = uAh + 32 * AWST;

    const int tid   = threadIdx.x;
    const int lane  = tid & 31;
    const int warp  = tid >> 5;
    const int r     = lane >> 2;
    const int q     = lane & 3;
    const int mt    = warp & 1;
    const int nt    = warp >> 1;
    const int bt    = blockIdx.x >> 5;
    const int ntile = blockIdx.x & 31;
    const int b0    = bt * 32;
    const int nBase = ntile * 32;
    const int dir   = ntile >> 4;
    const int gid   = bt * 2 + dir;

    // ---- split this CTA's W tile once ----
#pragma unroll
    for (int i = 0; i < 16; i++) {
        int idx = tid + i * 128;
        int m = idx >> 6, c4 = idx & 63;
        const float* src = WhhG + (size_t)(nBase + m) * HH + c4 * 8;
        float4 v0 = *(const float4*)src;
        float4 v1 = *(const float4*)(src + 4);
        unsigned hw[4], lw[4];
        f16split2(v0.x, v0.y, hw[0], lw[0]);
        f16split2(v0.z, v0.w, hw[1], lw[1]);
        f16split2(v1.x, v1.y, hw[2], lw[2]);
        f16split2(v1.z, v1.w, hw[3], lw[3]);
        *(uint4*)&uWh[m * AWST + c4 * 4] = make_uint4(hw[0], hw[1], hw[2], hw[3]);
        *(uint4*)&uWl[m * AWST + c4 * 4] = make_uint4(lw[0], lw[1], lw[2], lw[3]);
    }
    __syncthreads();

    const int brow0 = b0 + mt * 16 + r;
    const int colB  = nBase + nt * 16 + q * 2;
    const int wpCol = colB >> 1;
    const int arow0 = (mt * 16 + r) * AWST;
    const int arow1 = (mt * 16 + 8 + r) * AWST;
    const int nrow0 = (nt * 16 + r) * AWST;
    const int nrow1 = (nt * 16 + 8 + r) * AWST;

    unsigned dstH[2][8], dstL[2][8];
#pragma unroll
    for (int p = 0; p < 2; p++)
#pragma unroll
        for (int i = 0; i < 8; i++) {
            int idx = tid + i * 128;
            int m = idx >> 5;
            int c4 = (idx & 31) + p * 32;
            dstH[p][i] = (unsigned)__cvta_generic_to_shared(&uAh[m * AWST + c4 * 4]);
            dstL[p][i] = (unsigned)__cvta_generic_to_shared(&uAl[m * AWST + c4 * 4]);
        }

    for (int t = 0; t < TT; t++) {
        // ---- gate: this timestep's P tiles must be written (8 gemm blocks) ----
        if (tid == 0) {
            const int* pr = &pReady[t];
            while (ld_acq(pr) < 8) __nanosleep(64);
        }
        __syncthreads();

        const unsigned *HinH, *HinL;
        if (t == 0)           { HinH = h0H16; HinL = h0L16; }
        else if ((t - 1) & 1) { HinH = HhB; HinL = HlB; }
        else                  { HinH = HhA; HinL = HlA; }
        unsigned* HoutH = (t & 1) ? HhB : HhA;
        unsigned* HoutL = (t & 1) ? HlB : HlA;
        float* Fout = LAYER0 ? (Hbuf + (size_t)t * BB * NH)
                             : ((t & 1) ? f32B : f32A);

        // ---- stage A in two k-phases ----
        const uint4* gH = (const uint4*)HinH;
        const uint4* gL = (const uint4*)HinL;
#pragma unroll
        for (int p = 0; p < 2; p++) {
#pragma unroll
            for (int i = 0; i < 8; i++) {
                int idx = tid + i * 128;
                int m = idx >> 5;
                int c4 = (idx & 31) + p * 32;
                size_t gi = (size_t)(b0 + m) * 128 + dir * 64 + c4;
                cp16(dstH[p][i], gH + gi);
                cp16(dstL[p][i], gL + gi);
            }
            asm volatile("cp.async.commit_group;" ::: "memory");
        }

        const float* Pt = P + (size_t)t * BB * NH;
        float2 pv[2][2];
#pragma unroll
        for (int sub = 0; sub < 2; sub++) {
            int c = colB + sub * 8;
            pv[sub][0] = *(const float2*)&Pt[(size_t)brow0 * NH + c];
            pv[sub][1] = *(const float2*)&Pt[(size_t)(brow0 + 8) * NH + c];
        }

        float acch[2][4], accm[2][4];
#pragma unroll
        for (int s = 0; s < 2; s++)
#pragma unroll
            for (int c = 0; c < 4; c++) { acch[s][c] = 0.f; accm[s][c] = 0.f; }

        asm volatile("cp.async.wait_group 1;" ::: "memory");
        __syncthreads();
#pragma unroll 4
        for (int kc = 0; kc < 16; kc++) {
            int base = kc * 8 + q;
            unsigned ah[4], al[4];
            ah[0] = uAh[arow0 + base];     ah[1] = uAh[arow1 + base];
            ah[2] = uAh[arow0 + base + 4]; ah[3] = uAh[arow1 + base + 4];
            al[0] = uAl[arow0 + base];     al[1] = uAl[arow1 + base];
            al[2] = uAl[arow0 + base + 4]; al[3] = uAl[arow1 + base + 4];
#pragma unroll
            for (int sub = 0; sub < 2; sub++) {
                int nr = (sub ? nrow1 : nrow0) + base;
                unsigned bh[2] = { uWh[nr], uWh[nr + 4] };
                unsigned bl[2] = { uWl[nr], uWl[nr + 4] };
                mma16(acch[sub], ah, bh);
                mma16(accm[sub], ah, bl);
                mma16(accm[sub], al, bh);
            }
        }
        asm volatile("cp.async.wait_group 0;" ::: "memory");
        __syncthreads();
#pragma unroll 4
        for (int kc = 16; kc < 32; kc++) {
            int base = kc * 8 + q;
            unsigned ah[4], al[4];
            ah[0] = uAh[arow0 + base];     ah[1] = uAh[arow1 + base];
            ah[2] = uAh[arow0 + base + 4]; ah[3] = uAh[arow1 + base + 4];
            al[0] = uAl[arow0 + base];     al[1] = uAl[arow1 + base];
            al[2] = uAl[arow0 + base + 4]; al[3] = uAl[arow1 + base + 4];
#pragma unroll
            for (int sub = 0; sub < 2; sub++) {
                int nr = (sub ? nrow1 : nrow0) + base;
                unsigned bh[2] = { uWh[nr], uWh[nr + 4] };
                unsigned bl[2] = { uWl[nr], uWl[nr + 4] };
                mma16(acch[sub], ah, bh);
                mma16(accm[sub], ah, bl);
                mma16(accm[sub], al, bh);
            }
        }

        // ---- epilogue: combine, +P, relu; publish fp16 hi/lo ----
        float o[2][4];
#pragma unroll
        for (int sub = 0; sub < 2; sub++) {
            o[sub][0] = fmaxf(acch[sub][0] + accm[sub][0] * (1.f / 2048.f) + pv[sub][0].x, 0.f);
            o[sub][1] = fmaxf(acch[sub][1] + accm[sub][1] * (1.f / 2048.f) + pv[sub][0].y, 0.f);
            o[sub][2] = fmaxf(acch[sub][2] + accm[sub][2] * (1.f / 2048.f) + pv[sub][1].x, 0.f);
            o[sub][3] = fmaxf(acch[sub][3] + accm[sub][3] * (1.f / 2048.f) + pv[sub][1].y, 0.f);
            unsigned hw, lw;
            int wp0 = brow0 * 512 + wpCol + sub * 4;
            int wp1 = (brow0 + 8) * 512 + wpCol + sub * 4;
            f16split2(o[sub][0], o[sub][1], hw, lw);
            __stcg(&HoutH[wp0], hw); __stcg(&HoutL[wp0], lw);
            f16split2(o[sub][2], o[sub][3], hw, lw);
            __stcg(&HoutH[wp1], hw); __stcg(&HoutL[wp1], lw);
        }

        __syncthreads();
        int* cp = &ctr[t * 8 + gid];
        if (tid == 0) red_rel(cp);          // group arrive (publishes fp16 stores)

        // f32 history store overlaps the barrier wait
        if (LAYER0 || t == TT - 1) {
#pragma unroll
            for (int sub = 0; sub < 2; sub++) {
                int c = colB + sub * 8;
                __stcg((float2*)&Fout[(size_t)brow0 * NH + c],       make_float2(o[sub][0], o[sub][1]));
                __stcg((float2*)&Fout[(size_t)(brow0 + 8) * NH + c], make_float2(o[sub][2], o[sub][3]));
            }
        }
        if (LAYER0) {
            __syncthreads();                 // all f32 stores issued
            if (tid == 0) red_rel(&hDone[t]); // H0[t] published for P1 gemm
        }

        if (tid == 0) {
            while (ld_acq(cp) < GNUM) __nanosleep(32);
        }
        __syncthreads();
    }
}

// ---------------- small GEMM for head ----------------
template<int ACT>
__global__ void __launch_bounds__(256) gemm_bias(
    const float* __restrict__ A, const float* __restrict__ W,
    const float* __restrict__ bias, float* __restrict__ C,
    int M, int N, int K)
{
    __shared__ float sA[16][68];
    __shared__ float sB[16][68];
    const int m0  = blockIdx.y * 64;
    const int n0  = blockIdx.x * 64;
    const int tid = threadIdx.x;
    const int lk  = tid & 15;
    const int lr  = tid >> 4;
    const int tx  = tid & 15;
    const int ty  = tid >> 4;

    float acc[4][4];
#pragma unroll
    for (int i = 0; i < 4; i++)
#pragma unroll
        for (int j = 0; j < 4; j++) acc[i][j] = 0.f;

    for (int k0 = 0; k0 < K; k0 += 16) {
#pragma unroll
        for (int rr = 0; rr < 4; rr++) {
            int m = m0 + lr + rr * 16;
            sA[lk][lr + rr * 16] = A[(size_t)m * K + k0 + lk];
            sB[lk][lr + rr * 16] = W[(size_t)(n0 + lr + rr * 16) * K + k0 + lk];
        }
        __syncthreads();
#pragma unroll
        for (int kk = 0; kk < 16; kk++) {
            float4 a4 = *(const float4*)&sA[kk][tx * 4];
            float4 b4 = *(const float4*)&sB[kk][ty * 4];
            float av[4] = {a4.x, a4.y, a4.z, a4.w};
            float bv[4] = {b4.x, b4.y, b4.z, b4.w};
#pragma unroll
            for (int i = 0; i < 4; i++)
#pragma unroll
                for (int j = 0; j < 4; j++) acc[i][j] += av[i] * bv[j];
        }
        __syncthreads();
    }

#pragma unroll
    for (int i = 0; i < 4; i++) {
        int m = m0 + tx * 4 + i;
        float4 v;
        float* vp = (float*)&v;
#pragma unroll
        for (int j = 0; j < 4; j++) {
            float t = acc[i][j] + bias[n0 + ty * 4 + j];
            if (ACT == 2) t = 1.f / (1.f + expf(-t));
            vp[j] = t;
        }
        *(float4*)&C[(size_t)m * N + n0 + ty * 4] = v;
    }
}

// ---------------- BatchNorm1d (training, biased var) + ReLU ----------------
__global__ void bn_relu(const float* __restrict__ V, const float* __restrict__ gw,
                        const float* __restrict__ bw, float* __restrict__ Y, int cols)
{
    int c = blockIdx.x;
    int t = threadIdx.x;
    float v = V[(size_t)t * cols + c];
    float s = v, ss = v * v;
#pragma unroll
    for (int o = 16; o > 0; o >>= 1) {
        s  += __shfl_down_sync(0xffffffffu, s,  o);
        ss += __shfl_down_sync(0xffffffffu, ss, o);
    }
    __shared__ float rs[4], rq[4];
    if ((t & 31) == 0) { rs[t >> 5] = s; rq[t >> 5] = ss; }
    __syncthreads();
    float S = rs[0] + rs[1] + rs[2] + rs[3];
    float Q = rq[0] + rq[1] + rq[2] + rq[3];
    float mean = S * (1.f / BB);
    float var  = Q * (1.f / BB) - mean * mean;
    float y = (v - mean) * rsqrtf(var + EPSF) * gw[c] + bw[c];
    Y[(size_t)t * cols + c] = fmaxf(y, 0.f);
}

// ---------------- launch ----------------
extern "C" void kernel_launch(void* const* d_in, const int* in_sizes, int n_in,
                              void* d_out, int out_size)
{
    (void)in_sizes; (void)n_in; (void)out_size;
    const float* x     = (const float*)d_in[0];
    const float* h0    = (const float*)d_in[1];
    const float* W_ih0 = (const float*)d_in[2];
    const float* W_hh0 = (const float*)d_in[3];
    const float* b_ih0 = (const float*)d_in[4];
    const float* b_hh0 = (const float*)d_in[5];
    const float* W_ih1 = (const float*)d_in[6];
    const float* W_hh1 = (const float*)d_in[7];
    const float* b_ih1 = (const float*)d_in[8];
    const float* b_hh1 = (const float*)d_in[9];
    const float* bn1_g = (const float*)d_in[10];
    const float* bn1_b = (const float*)d_in[11];
    const float* fc1_W = (const float*)d_in[12];
    const float* fc1_b = (const float*)d_in[13];
    const float* bn2_g = (const float*)d_in[14];
    const float* bn2_b = (const float*)d_in[15];
    const float* fc2_W = (const float*)d_in[16];
    const float* fc2_b = (const float*)d_in[17];
    float* out = (float*)d_out;

    float *P, *H0p, *h1a, *h1b, *bs0, *bs1, *y1, *z;
    unsigned *h016h, *h016l, *h116h, *h116l, *HhA, *HhB, *HlA, *HlB;
    unsigned *Hh1A, *Hh1B, *Hl1A, *Hl1B;
    int *c0, *c1, *pf0, *pf1, *hdone;
    cudaGetSymbolAddress((void**)&P,     g_P);
    cudaGetSymbolAddress((void**)&H0p,   g_H0buf);
    cudaGetSymbolAddress((void**)&h016h, g_h016h);
    cudaGetSymbolAddress((void**)&h016l, g_h016l);
    cudaGetSymbolAddress((void**)&h116h, g_h116h);
    cudaGetSymbolAddress((void**)&h116l, g_h116l);
    cudaGetSymbolAddress((void**)&HhA,   g_HhA);
    cudaGetSymbolAddress((void**)&HhB,   g_HhB);
    cudaGetSymbolAddress((void**)&HlA,   g_HlA);
    cudaGetSymbolAddress((void**)&HlB,   g_HlB);
    cudaGetSymbolAddress((void**)&Hh1A,  g_Hh1A);
    cudaGetSymbolAddress((void**)&Hh1B,  g_Hh1B);
    cudaGetSymbolAddress((void**)&Hl1A,  g_Hl1A);
    cudaGetSymbolAddress((void**)&Hl1B,  g_Hl1B);
    cudaGetSymbolAddress((void**)&h1a,   g_h1a);
    cudaGetSymbolAddress((void**)&h1b,   g_h1b);
    cudaGetSymbolAddress((void**)&bs0,   g_bias0);
    cudaGetSymbolAddress((void**)&bs1,   g_bias1);
    cudaGetSymbolAddress((void**)&y1,    g_y1);
    cudaGetSymbolAddress((void**)&z,     g_z);
    cudaGetSymbolAddress((void**)&c0,    g_ctr0);
    cudaGetSymbolAddress((void**)&c1,    g_ctr1);
    cudaGetSymbolAddress((void**)&pf0,   g_pf0);
    cudaGetSymbolAddress((void**)&pf1,   g_pf1);
    cudaGetSymbolAddress((void**)&hdone, g_hdone);

    cudaFuncSetAttribute(rnn_mma<1>, cudaFuncAttributeMaxDynamicSharedMemorySize, RNN_SMEM);
    cudaFuncSetAttribute(rnn_mma<0>, cudaFuncAttributeMaxDynamicSharedMemorySize, RNN_SMEM);

    // 0) setup (plain)
    setup_kernel<<<256, 256>>>(h0, b_ih0, b_hh0, b_ih1, b_hh1);

    // 1) P0 (plain; serial after setup). Produces pf0[t].
    gemm_tc<1><<<dim3(NH / 128, M_BIG / 128), 256>>>(x, W_ih0, bs0, P, M_BIG, NH, IND,
                                                     (const int*)nullptr, 0, pf0);

    // PDL config helper
    cudaLaunchAttribute pdlAttr[1];
    pdlAttr[0].id = cudaLaunchAttributeProgrammaticStreamSerialization;
    pdlAttr[0].val.programmaticStreamSerializationAllowed = 1;

    // 2) layer-0 recurrence (PDL: may overlap P0's tail; gated per-t on pf0)
    {
        cudaLaunchConfig_t cfg = {};
        cfg.gridDim = dim3(NCTA, 1, 1);
        cfg.blockDim = dim3(128, 1, 1);
        cfg.dynamicSmemBytes = RNN_SMEM;
        cfg.stream = 0;
        cfg.attrs = pdlAttr; cfg.numAttrs = 1;
        const float* a0 = P;  const float* a1 = W_hh0;
        const unsigned* a2 = h016h; const unsigned* a3 = h016l;
        float* a4 = H0p; float* a5 = nullptr; float* a6 = nullptr;
        unsigned* a7 = HhA; unsigned* a8 = HhB; unsigned* a9 = HlA; unsigned* a10 = HlB;
        int* a11 = c0; const int* a12 = pf0; int* a13 = hdone;
        void* args[] = {&a0,&a1,&a2,&a3,&a4,&a5,&a6,&a7,&a8,&a9,&a10,&a11,&a12,&a13};
        cudaLaunchKernelExC(&cfg, (const void*)rnn_mma<1>, args);
    }

    // 3) P1 (PDL: overlaps rnn<1>; block y=t gated on hdone[t]==128). Produces pf1[t].
    {
        cudaLaunchConfig_t cfg = {};
        cfg.gridDim = dim3(NH / 128, M_BIG / 128, 1);
        cfg.blockDim = dim3(256, 1, 1);
        cfg.dynamicSmemBytes = 0;
        cfg.stream = 0;
        cfg.attrs = pdlAttr; cfg.numAttrs = 1;
        const float* a0 = H0p; const float* a1 = W_ih1; const float* a2 = bs1;
        float* a3 = P; int a4 = M_BIG, a5 = NH, a6 = NH;
        const int* a7 = hdone; int a8 = NCTA; int* a9 = pf1;
        void* args[] = {&a0,&a1,&a2,&a3,&a4,&a5,&a6,&a7,&a8,&a9};
        cudaLaunchKernelExC(&cfg, (const void*)gemm_tc<0>, args);
    }

    // 4) layer-1 recurrence (PDL; gated per-t on pf1). Own fp16 ping-pong buffers.
    {
        cudaLaunchConfig_t cfg = {};
        cfg.gridDim = dim3(NCTA, 1, 1);
        cfg.blockDim = dim3(128, 1, 1);
        cfg.dynamicSmemBytes = RNN_SMEM;
        cfg.stream = 0;
        cfg.attrs = pdlAttr; cfg.numAttrs = 1;
        const float* a0 = P;  const float* a1 = W_hh1;
        const unsigned* a2 = h116h; const unsigned* a3 = h116l;
        float* a4 = nullptr; float* a5 = h1a; float* a6 = h1b;
        unsigned* a7 = Hh1A; unsigned* a8 = Hh1B; unsigned* a9 = Hl1A; unsigned* a10 = Hl1B;
        int* a11 = c1; const int* a12 = pf1; int* a13 = nullptr;
        void* args[] = {&a0,&a1,&a2,&a3,&a4,&a5,&a6,&a7,&a8,&a9,&a10,&a11,&a12,&a13};
        cudaLaunchKernelExC(&cfg, (const void*)rnn_mma<0>, args);
    }

    // 5) head (plain launches: wait for rnn<0> completion)
    bn_relu<<<NH, 128>>>(h1b, bn1_g, bn1_b, y1, NH);
    gemm_bias<0><<<dim3(FC1N / 64, BB / 64), 256>>>(y1, fc1_W, fc1_b, z, BB, FC1N, NH);
    bn_relu<<<FC1N, 128>>>(z, bn2_g, bn2_b, z, FC1N);
    gemm_bias<2><<<dim3(OUTN / 64, BB / 64), 256>>>(z, fc2_W, fc2_b, out, BB, OUTN, FC1N);
}

// round 16
// speedup vs baseline: 1.1694x; 1.1694x over previous
#include <cuda_runtime.h>
#include <cuda_fp16.h>
#include <math.h>

#define BB    128
#define TT    1024
#define IND   256
#define HH    512
#define NH    1024          // 2*H
#define FC1N  2048
#define OUTN  128
#define EPSF  1e-5f

#define M_BIG (TT * BB)
#define NCTA  128
#define GNUM  16            // CTAs per sync group (bt x direction)

// fp16 recurrence smem: 4 arrays of [32 rows][264 words]
#define AWST  264
#define RNN_SMEM (4 * 32 * AWST * 4)    // 135,168 bytes

#define HWORDS (BB * 512)   // words per timestep slice of fp16 history (65536)

// gemm_f16 dynamic smem: A hi/lo [128][GFST] + W hi/lo [64][GFST]
#define GFST  36
#define GF_SMEM ((2 * 128 * GFST + 2 * 64 * GFST) * 4)   // 55,296 bytes

// ---- tf32 split (gemm_tc; R7/R8-verified) ----
__device__ __forceinline__ void tf32_split(float x, unsigned &hi, unsigned &lo) {
    unsigned h;
    asm("cvt.rna.tf32.f32 %0, %1;" : "=r"(h) : "f"(x));
    float rem = x - __uint_as_float(h);
    unsigned l;
    asm("cvt.rna.tf32.f32 %0, %1;" : "=r"(l) : "f"(rem));
    hi = h; lo = l;
}

__device__ __forceinline__ void mma8(float* d, const unsigned* a, const unsigned* b) {
    asm volatile(
        "mma.sync.aligned.m16n8k8.row.col.f32.tf32.tf32.f32 "
        "{%0,%1,%2,%3}, {%4,%5,%6,%7}, {%8,%9}, {%0,%1,%2,%3};"
        : "+f"(d[0]), "+f"(d[1]), "+f"(d[2]), "+f"(d[3])
        : "r"(a[0]), "r"(a[1]), "r"(a[2]), "r"(a[3]), "r"(b[0]), "r"(b[1]));
}

__device__ __forceinline__ void mma16(float* d, const unsigned* a, const unsigned* b) {
    asm volatile(
        "mma.sync.aligned.m16n8k16.row.col.f32.f16.f16.f32 "
        "{%0,%1,%2,%3}, {%4,%5,%6,%7}, {%8,%9}, {%0,%1,%2,%3};"
        : "+f"(d[0]), "+f"(d[1]), "+f"(d[2]), "+f"(d[3])
        : "r"(a[0]), "r"(a[1]), "r"(a[2]), "r"(a[3]), "r"(b[0]), "r"(b[1]));
}

__device__ __forceinline__ void f16split2(float x0, float x1, unsigned &hw, unsigned &lw) {
    __half a0 = __float2half_rn(x0);
    __half a1 = __float2half_rn(x1);
    float r0 = (x0 - __half2float(a0)) * 2048.f;
    float r1 = (x1 - __half2float(a1)) * 2048.f;
    __half b0 = __float2half_rn(r0);
    __half b1 = __float2half_rn(r1);
    hw = ((unsigned)__half_as_ushort(a1) << 16) | (unsigned)__half_as_ushort(a0);
    lw = ((unsigned)__half_as_ushort(b1) << 16) | (unsigned)__half_as_ushort(b0);
}

__device__ __forceinline__ void cp16(unsigned smem_addr, const void* gptr) {
    asm volatile("cp.async.cg.shared.global [%0], [%1], 16;"
                 :: "r"(smem_addr), "l"(gptr));
}

__device__ __forceinline__ int ld_acq(const int* p) {
    int v;
    asm volatile("ld.acquire.gpu.global.s32 %0, [%1];" : "=r"(v) : "l"(p) : "memory");
    return v;
}
__device__ __forceinline__ void red_rel(int* p) {
    asm volatile("red.release.gpu.global.add.s32 [%0], %1;" :: "l"(p), "r"(1) : "memory");
}

// ---------------- device scratch ----------------
__device__ float    g_P[TT * BB * NH];          // 512 MB: P0 then P1
__device__ unsigned g_H16h[TT * HWORDS];        // 256 MB: layer-0 fp16-hi history
__device__ unsigned g_H16l[TT * HWORDS];        // 256 MB: layer-0 fp16-lo history
__device__ unsigned g_h016h[BB * NH / 2];
__device__ unsigned g_h016l[BB * NH / 2];
__device__ unsigned g_h116h[BB * NH / 2];
__device__ unsigned g_h116l[BB * NH / 2];
__device__ unsigned g_HhA[BB * NH / 2];         // layer-1 fp16 ping-pong
__device__ unsigned g_HhB[BB * NH / 2];
__device__ unsigned g_HlA[BB * NH / 2];
__device__ unsigned g_HlB[BB * NH / 2];
__device__ float    g_h1a[BB * NH];
__device__ float    g_h1b[BB * NH];
__device__ float    g_bias0[NH];
__device__ float    g_bias1[NH];
__device__ float    g_y1[BB * NH];
__device__ float    g_z[BB * FC1N];
__device__ int      g_ctr0[TT * 8];
__device__ int      g_ctr1[TT * 8];

// ---------------- setup ----------------
__global__ void setup_kernel(const float* __restrict__ h0,
                             const float* __restrict__ bih0, const float* __restrict__ bhh0,
                             const float* __restrict__ bih1, const float* __restrict__ bhh1)
{
    int i0 = blockIdx.x * blockDim.x + threadIdx.x;
    if (i0 < NH) {
        g_bias0[i0] = bih0[i0] + bhh0[i0];
        g_bias1[i0] = bih1[i0] + bhh1[i0];
    }
    if (i0 < TT * 8) { g_ctr0[i0] = 0; g_ctr1[i0] = 0; }
    int stride = gridDim.x * blockDim.x;
    for (int wi = i0; wi < BB * (NH / 2); wi += stride) {
        int b  = wi >> 9;
        int kp = wi & 511;
        int d  = kp >> 8;
        int j0 = (kp * 2) & (HH - 1);
        float v0a = h0[(size_t)(d * BB + b) * HH + j0];
        float v0b = h0[(size_t)(d * BB + b) * HH + j0 + 1];
        float v1a = h0[(size_t)((2 + d) * BB + b) * HH + j0];
        float v1b = h0[(size_t)((2 + d) * BB + b) * HH + j0 + 1];
        unsigned hw, lw;
        f16split2(v0a, v0b, hw, lw);
        g_h016h[wi] = hw; g_h016l[wi] = lw;
        f16split2(v1a, v1b, hw, lw);
        g_h116h[wi] = hw; g_h116l[wi] = lw;
    }
}

// ---------------- tensor-core GEMM (tf32x3) for P0 -- R13 form ----------------
#define SK 20
template<int AMODE>
__global__ void __launch_bounds__(256) gemm_tc(
    const float* __restrict__ A, const float* __restrict__ W,
    const float* __restrict__ bias, float* __restrict__ C,
    int M, int N, int K)
{
    __shared__ unsigned sAh[128][SK];
    __shared__ unsigned sAl[128][SK];
    __shared__ unsigned sWh[128][SK];
    __shared__ unsigned sWl[128][SK];

    const int m0   = blockIdx.y * 128;
    const int n0   = blockIdx.x * 128;
    const int tid  = threadIdx.x;
    const int lane = tid & 31;
    const int warp = tid >> 5;
    const int wm   = (warp & 1) * 64;
    const int wn   = (warp >> 1) * 32;
    const int r    = lane >> 2;
    const int q    = lane & 3;

    const int srow = tid >> 1;
    const int scg  = (tid & 1) * 8;

    float acc[4][4][4];
#pragma unroll
    for (int i = 0; i < 4; i++)
#pragma unroll
        for (int j = 0; j < 4; j++)
#pragma unroll
            for (int c = 0; c < 4; c++) acc[i][j][c] = 0.f;

    const float* arow;
    {
        int m = m0 + srow;
        if (AMODE == 1) arow = A + ((size_t)((m & (BB - 1)) * TT + (m >> 7))) * K;
        else            arow = A + (size_t)m * K;
    }
    const float* wrow = W + (size_t)(n0 + srow) * K;

    for (int k0 = 0; k0 < K; k0 += 16) {
        float4 av0 = *(const float4*)&arow[k0 + scg];
        float4 av1 = *(const float4*)&arow[k0 + scg + 4];
        float4 wv0 = *(const float4*)&wrow[k0 + scg];
        float4 wv1 = *(const float4*)&wrow[k0 + scg + 4];
        const float* af = (const float*)&av0;
#pragma unroll
        for (int j = 0; j < 4; j++) tf32_split(af[j], sAh[srow][scg + j], sAl[srow][scg + j]);
        af = (const float*)&av1;
#pragma unroll
        for (int j = 0; j < 4; j++) tf32_split(af[j], sAh[srow][scg + 4 + j], sAl[srow][scg + 4 + j]);
        const float* wf = (const float*)&wv0;
#pragma unroll
        for (int j = 0; j < 4; j++) tf32_split(wf[j], sWh[srow][scg + j], sWl[srow][scg + j]);
        wf = (const float*)&wv1;
#pragma unroll
        for (int j = 0; j < 4; j++) tf32_split(wf[j], sWh[srow][scg + 4 + j], sWl[srow][scg + 4 + j]);
        __syncthreads();

#pragma unroll
        for (int kk = 0; kk < 16; kk += 8) {
            unsigned bh[4][2], bl[4][2];
#pragma unroll
            for (int nt = 0; nt < 4; nt++) {
                int nn = wn + nt * 8 + r;
                bh[nt][0] = sWh[nn][kk + q];
                bh[nt][1] = sWh[nn][kk + q + 4];
                bl[nt][0] = sWl[nn][kk + q];
                bl[nt][1] = sWl[nn][kk + q + 4];
            }
#pragma unroll
            for (int mt = 0; mt < 4; mt++) {
                int mm = wm + mt * 16 + r;
                unsigned ah[4], al[4];
                ah[0] = sAh[mm][kk + q];     ah[1] = sAh[mm + 8][kk + q];
                ah[2] = sAh[mm][kk + q + 4]; ah[3] = sAh[mm + 8][kk + q + 4];
                al[0] = sAl[mm][kk + q];     al[1] = sAl[mm + 8][kk + q];
                al[2] = sAl[mm][kk + q + 4]; al[3] = sAl[mm + 8][kk + q + 4];
#pragma unroll
                for (int nt = 0; nt < 4; nt++) {
                    mma8(acc[mt][nt], ah, bh[nt]);
                    mma8(acc[mt][nt], ah, bl[nt]);
                    mma8(acc[mt][nt], al, bh[nt]);
                }
            }
        }
        __syncthreads();
    }

#pragma unroll
    for (int mt = 0; mt < 4; mt++) {
#pragma unroll
        for (int nt = 0; nt < 4; nt++) {
            int n  = n0 + wn + nt * 8 + q * 2;
            int ml = m0 + wm + mt * 16 + r;
            float bx = bias[n], by = bias[n + 1];
            float2 o0 = make_float2(acc[mt][nt][0] + bx, acc[mt][nt][1] + by);
            float2 o1 = make_float2(acc[mt][nt][2] + bx, acc[mt][nt][3] + by);
            *(float2*)&C[(size_t)ml * N + n]       = o0;
            *(float2*)&C[(size_t)(ml + 8) * N + n] = o1;
        }
    }
}

// ---------------- fp16x3 GEMM for P1: C = (Ah + Al/2048) @ W^T + bias ----------------
// A given as packed-fp16 word arrays [M][512]. CTA 128m x 64n, warp m64 x n16,
// BK=64 (32 words). DYNAMIC smem (55,296 B > 48 KB static limit).
__global__ void __launch_bounds__(256, 2) gemm_f16(
    const unsigned* __restrict__ Ah, const unsigned* __restrict__ Al,
    const float* __restrict__ W, const float* __restrict__ bias,
    float* __restrict__ C, int M, int N, int K)
{
    extern __shared__ unsigned gsm[];
    unsigned* sAh = gsm;                      // [128][GFST]
    unsigned* sAl = sAh + 128 * GFST;
    unsigned* sWh = sAl + 128 * GFST;         // [64][GFST]
    unsigned* sWl = sWh + 64 * GFST;

    const int m0   = blockIdx.y * 128;
    const int n0   = blockIdx.x * 64;
    const int tid  = threadIdx.x;
    const int lane = tid & 31;
    const int warp = tid >> 5;
    const int r    = lane >> 2;
    const int q    = lane & 3;
    const int wm   = (warp & 1) * 64;     // 2 warps over m (4 m16 tiles each)
    const int wn   = (warp >> 1) * 16;    // 4 warps over n (2 n8 tiles each)

    // A staging: 2 threads per row, 16 words each (4 cp.async per array)
    const int am   = tid >> 1;
    const int aoff = (tid & 1) * 16;
    // W staging: 4 threads per row, 16 floats -> 8 words each
    const int wr   = tid >> 2;
    const int woff = (tid & 3) * 8;
    const int wkof = (tid & 3) * 16;

    unsigned aDstH[4], aDstL[4];
#pragma unroll
    for (int j = 0; j < 4; j++) {
        aDstH[j] = (unsigned)__cvta_generic_to_shared(&sAh[am * GFST + aoff + 4 * j]);
        aDstL[j] = (unsigned)__cvta_generic_to_shared(&sAl[am * GFST + aoff + 4 * j]);
    }

    float acch[4][2][4], accm[4][2][4];
#pragma unroll
    for (int mt = 0; mt < 4; mt++)
#pragma unroll
        for (int nt = 0; nt < 2; nt++)
#pragma unroll
            for (int c = 0; c < 4; c++) { acch[mt][nt][c] = 0.f; accm[mt][nt][c] = 0.f; }

    const unsigned* aRowH = Ah + (size_t)(m0 + am) * 512 + aoff;
    const unsigned* aRowL = Al + (size_t)(m0 + am) * 512 + aoff;
    const float*    wRow  = W + (size_t)(n0 + wr) * K + wkof;

    for (int kw = 0; kw < 512; kw += 32) {      // kw = word offset (64 k per iter)
        // A: pure copies (already fp16 hi/lo)
#pragma unroll
        for (int j = 0; j < 4; j++) {
            cp16(aDstH[j], aRowH + kw + 4 * j);
            cp16(aDstL[j], aRowL + kw + 4 * j);
        }
        asm volatile("cp.async.commit_group;" ::: "memory");

        // W: load f32, split to fp16 hi/lo words
        const float* wp = wRow + kw * 2;
#pragma unroll
        for (int j = 0; j < 4; j++) {
            float4 v = *(const float4*)(wp + 4 * j);
            unsigned hw0, lw0, hw1, lw1;
            f16split2(v.x, v.y, hw0, lw0);
            f16split2(v.z, v.w, hw1, lw1);
            sWh[wr * GFST + woff + 2 * j]     = hw0;
            sWl[wr * GFST + woff + 2 * j]     = lw0;
            sWh[wr * GFST + woff + 2 * j + 1] = hw1;
            sWl[wr * GFST + woff + 2 * j + 1] = lw1;
        }
        asm volatile("cp.async.wait_group 0;" ::: "memory");
        __syncthreads();

#pragma unroll
        for (int kc = 0; kc < 4; kc++) {        // 4 k16 chunks
            int base = kc * 8 + q;
            unsigned bh[2][2], bl[2][2];
#pragma unroll
            for (int nt = 0; nt < 2; nt++) {
                int nr = (wn + nt * 8 + r) * GFST + base;
                bh[nt][0] = sWh[nr];
                bh[nt][1] = sWh[nr + 4];
                bl[nt][0] = sWl[nr];
                bl[nt][1] = sWl[nr + 4];
            }
#pragma unroll
            for (int mt = 0; mt < 4; mt++) {
                int mr = (wm + mt * 16 + r) * GFST + base;
                int mr8 = mr + 8 * GFST;
                unsigned ah[4], al[4];
                ah[0] = sAh[mr];     ah[1] = sAh[mr8];
                ah[2] = sAh[mr + 4]; ah[3] = sAh[mr8 + 4];
                al[0] = sAl[mr];     al[1] = sAl[mr8];
                al[2] = sAl[mr + 4]; al[3] = sAl[mr8 + 4];
#pragma unroll
                for (int nt = 0; nt < 2; nt++) {
                    mma16(acch[mt][nt], ah, bh[nt]);
                    mma16(accm[mt][nt], ah, bl[nt]);
                    mma16(accm[mt][nt], al, bh[nt]);
                }
            }
        }
        __syncthreads();
    }

#pragma unroll
    for (int mt = 0; mt < 4; mt++)
#pragma unroll
        for (int nt = 0; nt < 2; nt++) {
            int n  = n0 + wn + nt * 8 + q * 2;
            int ml = m0 + wm + mt * 16 + r;
            float bx = bias[n], by = bias[n + 1];
            float2 o0, o1;
            o0.x = acch[mt][nt][0] + accm[mt][nt][0] * (1.f / 2048.f) + bx;
            o0.y = acch[mt][nt][1] + accm[mt][nt][1] * (1.f / 2048.f) + by;
            o1.x = acch[mt][nt][2] + accm[mt][nt][2] * (1.f / 2048.f) + bx;
            o1.y = acch[mt][nt][3] + accm[mt][nt][3] * (1.f / 2048.f) + by;
            *(float2*)&C[(size_t)ml * N + n]       = o0;
            *(float2*)&C[(size_t)(ml + 8) * N + n] = o1;
        }
}

// ---------------- persistent recurrence: fp16x3 (R13 core) ----------------
// LAYER0: history mode — writes fp16 hi/lo history slices, reads slice t-1.
// LAYER1: ping-pong fp16; f32 output only at t = TT-1.
template<int LAYER0>
__global__ void __launch_bounds__(128, 1) rnn_mma(
    const float* __restrict__ P, const float* __restrict__ WhhG,
    const unsigned* __restrict__ h0H16, const unsigned* __restrict__ h0L16,
    unsigned* __restrict__ HistH, unsigned* __restrict__ HistL,
    float* __restrict__ f32A, float* __restrict__ f32B,
    unsigned* __restrict__ HhA, unsigned* __restrict__ HhB,
    unsigned* __restrict__ HlA, unsigned* __restrict__ HlB,
    int* __restrict__ ctr)
{
    extern __shared__ unsigned usm[];
    unsigned* uWh = usm;                    // [32][AWST]
    unsigned* uWl = uWh + 32 * AWST;
    unsigned* uAh = uWl + 32 * AWST;
    unsigned* uAl = uAh + 32 * AWST;

    const int tid   = threadIdx.x;
    const int lane  = tid & 31;
    const int warp  = tid >> 5;
    const int r     = lane >> 2;
    const int q     = lane & 3;
    const int mt    = warp & 1;
    const int nt    = warp >> 1;
    const int bt    = blockIdx.x >> 5;
    const int ntile = blockIdx.x & 31;
    const int b0    = bt * 32;
    const int nBase = ntile * 32;
    const int dir   = ntile >> 4;
    const int gid   = bt * 2 + dir;

    // ---- split this CTA's W tile once ----
#pragma unroll
    for (int i = 0; i < 16; i++) {
        int idx = tid + i * 128;
        int m = idx >> 6, c4 = idx & 63;
        const float* src = WhhG + (size_t)(nBase + m) * HH + c4 * 8;
        float4 v0 = *(const float4*)src;
        float4 v1 = *(const float4*)(src + 4);
        unsigned hw[4], lw[4];
        f16split2(v0.x, v0.y, hw[0], lw[0]);
        f16split2(v0.z, v0.w, hw[1], lw[1]);
        f16split2(v1.x, v1.y, hw[2], lw[2]);
        f16split2(v1.z, v1.w, hw[3], lw[3]);
        *(uint4*)&uWh[m * AWST + c4 * 4] = make_uint4(hw[0], hw[1], hw[2], hw[3]);
        *(uint4*)&uWl[m * AWST + c4 * 4] = make_uint4(lw[0], lw[1], lw[2], lw[3]);
    }
    __syncthreads();

    const int brow0 = b0 + mt * 16 + r;
    const int colB  = nBase + nt * 16 + q * 2;
    const int wpCol = colB >> 1;
    const int arow0 = (mt * 16 + r) * AWST;
    const int arow1 = (mt * 16 + 8 + r) * AWST;
    const int nrow0 = (nt * 16 + r) * AWST;
    const int nrow1 = (nt * 16 + 8 + r) * AWST;

    unsigned dstH[2][8], dstL[2][8];
#pragma unroll
    for (int p = 0; p < 2; p++)
#pragma unroll
        for (int i = 0; i < 8; i++) {
            int idx = tid + i * 128;
            int m = idx >> 5;
            int c4 = (idx & 31) + p * 32;
            dstH[p][i] = (unsigned)__cvta_generic_to_shared(&uAh[m * AWST + c4 * 4]);
            dstL[p][i] = (unsigned)__cvta_generic_to_shared(&uAl[m * AWST + c4 * 4]);
        }

    for (int t = 0; t < TT; t++) {
        const unsigned *HinH, *HinL;
        unsigned *HoutH, *HoutL;
        if (LAYER0) {
            HinH = (t == 0) ? h0H16 : (HistH + (size_t)(t - 1) * HWORDS);
            HinL = (t == 0) ? h0L16 : (HistL + (size_t)(t - 1) * HWORDS);
            HoutH = HistH + (size_t)t * HWORDS;
            HoutL = HistL + (size_t)t * HWORDS;
        } else {
            if (t == 0)           { HinH = h0H16; HinL = h0L16; }
            else if ((t - 1) & 1) { HinH = HhB; HinL = HlB; }
            else                  { HinH = HhA; HinL = HlA; }
            HoutH = (t & 1) ? HhB : HhA;
            HoutL = (t & 1) ? HlB : HlA;
        }

        // ---- stage A in two k-phases ----
        const uint4* gH = (const uint4*)HinH;
        const uint4* gL = (const uint4*)HinL;
#pragma unroll
        for (int p = 0; p < 2; p++) {
#pragma unroll
            for (int i = 0; i < 8; i++) {
                int idx = tid + i * 128;
                int m = idx >> 5;
                int c4 = (idx & 31) + p * 32;
                size_t gi = (size_t)(b0 + m) * 128 + dir * 64 + c4;
                cp16(dstH[p][i], gH + gi);
                cp16(dstL[p][i], gL + gi);
            }
            asm volatile("cp.async.commit_group;" ::: "memory");
        }

        const float* Pt = P + (size_t)t * BB * NH;
        float2 pv[2][2];
#pragma unroll
        for (int sub = 0; sub < 2; sub++) {
            int c = colB + sub * 8;
            pv[sub][0] = *(const float2*)&Pt[(size_t)brow0 * NH + c];
            pv[sub][1] = *(const float2*)&Pt[(size_t)(brow0 + 8) * NH + c];
        }

        float acch[2][4], accm[2][4];
#pragma unroll
        for (int s = 0; s < 2; s++)
#pragma unroll
            for (int c = 0; c < 4; c++) { acch[s][c] = 0.f; accm[s][c] = 0.f; }

        asm volatile("cp.async.wait_group 1;" ::: "memory");
        __syncthreads();
#pragma unroll 4
        for (int kc = 0; kc < 16; kc++) {
            int base = kc * 8 + q;
            unsigned ah[4], al[4];
            ah[0] = uAh[arow0 + base];     ah[1] = uAh[arow1 + base];
            ah[2] = uAh[arow0 + base + 4]; ah[3] = uAh[arow1 + base + 4];
            al[0] = uAl[arow0 + base];     al[1] = uAl[arow1 + base];
            al[2] = uAl[arow0 + base + 4]; al[3] = uAl[arow1 + base + 4];
#pragma unroll
            for (int sub = 0; sub < 2; sub++) {
                int nr = (sub ? nrow1 : nrow0) + base;
                unsigned bh[2] = { uWh[nr], uWh[nr + 4] };
                unsigned bl[2] = { uWl[nr], uWl[nr + 4] };
                mma16(acch[sub], ah, bh);
                mma16(accm[sub], ah, bl);
                mma16(accm[sub], al, bh);
            }
        }
        asm volatile("cp.async.wait_group 0;" ::: "memory");
        __syncthreads();
#pragma unroll 4
        for (int kc = 16; kc < 32; kc++) {
            int base = kc * 8 + q;
            unsigned ah[4], al[4];
            ah[0] = uAh[arow0 + base];     ah[1] = uAh[arow1 + base];
            ah[2] = uAh[arow0 + base + 4]; ah[3] = uAh[arow1 + base + 4];
            al[0] = uAl[arow0 + base];     al[1] = uAl[arow1 + base];
            al[2] = uAl[arow0 + base + 4]; al[3] = uAl[arow1 + base + 4];
#pragma unroll
            for (int sub = 0; sub < 2; sub++) {
                int nr = (sub ? nrow1 : nrow0) + base;
                unsigned bh[2] = { uWh[nr], uWh[nr + 4] };
                unsigned bl[2] = { uWl[nr], uWl[nr + 4] };
                mma16(acch[sub], ah, bh);
                mma16(accm[sub], ah, bl);
                mma16(accm[sub], al, bh);
            }
        }

        // ---- epilogue: combine, +P, relu; publish fp16 hi/lo ----
        float o[2][4];
#pragma unroll
        for (int sub = 0; sub < 2; sub++) {
            o[sub][0] = fmaxf(acch[sub][0] + accm[sub][0] * (1.f / 2048.f) + pv[sub][0].x, 0.f);
            o[sub][1] = fmaxf(acch[sub][1] + accm[sub][1] * (1.f / 2048.f) + pv[sub][0].y, 0.f);
            o[sub][2] = fmaxf(acch[sub][2] + accm[sub][2] * (1.f / 2048.f) + pv[sub][1].x, 0.f);
            o[sub][3] = fmaxf(acch[sub][3] + accm[sub][3] * (1.f / 2048.f) + pv[sub][1].y, 0.f);
            unsigned hw, lw;
            int wp0 = brow0 * 512 + wpCol + sub * 4;
            int wp1 = (brow0 + 8) * 512 + wpCol + sub * 4;
            f16split2(o[sub][0], o[sub][1], hw, lw);
            __stcg(&HoutH[wp0], hw); __stcg(&HoutL[wp0], lw);
            f16split2(o[sub][2], o[sub][3], hw, lw);
            __stcg(&HoutH[wp1], hw); __stcg(&HoutL[wp1], lw);
        }

        __syncthreads();
        int* cp = &ctr[t * 8 + gid];
        if (tid == 0) red_rel(cp);          // arrive (release publishes fp16 stores)

        // layer-1 final f32 state store overlaps the barrier wait
        if (!LAYER0 && t == TT - 1) {
            float* Fout = (t & 1) ? f32B : f32A;
#pragma unroll
            for (int sub = 0; sub < 2; sub++) {
                int c = colB + sub * 8;
                __stcg((float2*)&Fout[(size_t)brow0 * NH + c],       make_float2(o[sub][0], o[sub][1]));
                __stcg((float2*)&Fout[(size_t)(brow0 + 8) * NH + c], make_float2(o[sub][2], o[sub][3]));
            }
        }

        if (tid == 0) {
            while (ld_acq(cp) < GNUM) __nanosleep(32);
        }
        __syncthreads();
    }
}

// ---------------- small GEMM for head ----------------
template<int ACT>
__global__ void __launch_bounds__(256) gemm_bias(
    const float* __restrict__ A, const float* __restrict__ W,
    const float* __restrict__ bias, float* __restrict__ C,
    int M, int N, int K)
{
    __shared__ float sA[16][68];
    __shared__ float sB[16][68];
    const int m0  = blockIdx.y * 64;
    const int n0  = blockIdx.x * 64;
    const int tid = threadIdx.x;
    const int lk  = tid & 15;
    const int lr  = tid >> 4;
    const int tx  = tid & 15;
    const int ty  = tid >> 4;

    float acc[4][4];
#pragma unroll
    for (int i = 0; i < 4; i++)
#pragma unroll
        for (int j = 0; j < 4; j++) acc[i][j] = 0.f;

    for (int k0 = 0; k0 < K; k0 += 16) {
#pragma unroll
        for (int rr = 0; rr < 4; rr++) {
            int m = m0 + lr + rr * 16;
            sA[lk][lr + rr * 16] = A[(size_t)m * K + k0 + lk];
            sB[lk][lr + rr * 16] = W[(size_t)(n0 + lr + rr * 16) * K + k0 + lk];
        }
        __syncthreads();
#pragma unroll
        for (int kk = 0; kk < 16; kk++) {
            float4 a4 = *(const float4*)&sA[kk][tx * 4];
            float4 b4 = *(const float4*)&sB[kk][ty * 4];
            float av[4] = {a4.x, a4.y, a4.z, a4.w};
            float bv[4] = {b4.x, b4.y, b4.z, b4.w};
#pragma unroll
            for (int i = 0; i < 4; i++)
#pragma unroll
                for (int j = 0; j < 4; j++) acc[i][j] += av[i] * bv[j];
        }
        __syncthreads();
    }

#pragma unroll
    for (int i = 0; i < 4; i++) {
        int m = m0 + tx * 4 + i;
        float4 v;
        float* vp = (float*)&v;
#pragma unroll
        for (int j = 0; j < 4; j++) {
            float t = acc[i][j] + bias[n0 + ty * 4 + j];
            if (ACT == 2) t = 1.f / (1.f + expf(-t));
            vp[j] = t;
        }
        *(float4*)&C[(size_t)m * N + n0 + ty * 4] = v;
    }
}

// ---------------- BatchNorm1d (training, biased var) + ReLU ----------------
__global__ void bn_relu(const float* __restrict__ V, const float* __restrict__ gw,
                        const float* __restrict__ bw, float* __restrict__ Y, int cols)
{
    int c = blockIdx.x;
    int t = threadIdx.x;
    float v = V[(size_t)t * cols + c];
    float s = v, ss = v * v;
#pragma unroll
    for (int o = 16; o > 0; o >>= 1) {
        s  += __shfl_down_sync(0xffffffffu, s,  o);
        ss += __shfl_down_sync(0xffffffffu, ss, o);
    }
    __shared__ float rs[4], rq[4];
    if ((t & 31) == 0) { rs[t >> 5] = s; rq[t >> 5] = ss; }
    __syncthreads();
    float S = rs[0] + rs[1] + rs[2] + rs[3];
    float Q = rq[0] + rq[1] + rq[2] + rq[3];
    float mean = S * (1.f / BB);
    float var  = Q * (1.f / BB) - mean * mean;
    float y = (v - mean) * rsqrtf(var + EPSF) * gw[c] + bw[c];
    Y[(size_t)t * cols + c] = fmaxf(y, 0.f);
}

// ---------------- launch ----------------
extern "C" void kernel_launch(void* const* d_in, const int* in_sizes, int n_in,
                              void* d_out, int out_size)
{
    (void)in_sizes; (void)n_in; (void)out_size;
    const float* x     = (const float*)d_in[0];
    const float* h0    = (const float*)d_in[1];
    const float* W_ih0 = (const float*)d_in[2];
    const float* W_hh0 = (const float*)d_in[3];
    const float* b_ih0 = (const float*)d_in[4];
    const float* b_hh0 = (const float*)d_in[5];
    const float* W_ih1 = (const float*)d_in[6];
    const float* W_hh1 = (const float*)d_in[7];
    const float* b_ih1 = (const float*)d_in[8];
    const float* b_hh1 = (const float*)d_in[9];
    const float* bn1_g = (const float*)d_in[10];
    const float* bn1_b = (const float*)d_in[11];
    const float* fc1_W = (const float*)d_in[12];
    const float* fc1_b = (const float*)d_in[13];
    const float* bn2_g = (const float*)d_in[14];
    const float* bn2_b = (const float*)d_in[15];
    const float* fc2_W = (const float*)d_in[16];
    const float* fc2_b = (const float*)d_in[17];
    float* out = (float*)d_out;

    float *P, *h1a, *h1b, *bs0, *bs1, *y1, *z;
    unsigned *H16h, *H16l, *h016h, *h016l, *h116h, *h116l, *HhA, *HhB, *HlA, *HlB;
    int *c0, *c1;
    cudaGetSymbolAddress((void**)&P,     g_P);
    cudaGetSymbolAddress((void**)&H16h,  g_H16h);
    cudaGetSymbolAddress((void**)&H16l,  g_H16l);
    cudaGetSymbolAddress((void**)&h016h, g_h016h);
    cudaGetSymbolAddress((void**)&h016l, g_h016l);
    cudaGetSymbolAddress((void**)&h116h, g_h116h);
    cudaGetSymbolAddress((void**)&h116l, g_h116l);
    cudaGetSymbolAddress((void**)&HhA,   g_HhA);
    cudaGetSymbolAddress((void**)&HhB,   g_HhB);
    cudaGetSymbolAddress((void**)&HlA,   g_HlA);
    cudaGetSymbolAddress((void**)&HlB,   g_HlB);
    cudaGetSymbolAddress((void**)&h1a,   g_h1a);
    cudaGetSymbolAddress((void**)&h1b,   g_h1b);
    cudaGetSymbolAddress((void**)&bs0,   g_bias0);
    cudaGetSymbolAddress((void**)&bs1,   g_bias1);
    cudaGetSymbolAddress((void**)&y1,    g_y1);
    cudaGetSymbolAddress((void**)&z,     g_z);
    cudaGetSymbolAddress((void**)&c0,    g_ctr0);
    cudaGetSymbolAddress((void**)&c1,    g_ctr1);

    cudaFuncSetAttribute(rnn_mma<1>, cudaFuncAttributeMaxDynamicSharedMemorySize, RNN_SMEM);
    cudaFuncSetAttribute(rnn_mma<0>, cudaFuncAttributeMaxDynamicSharedMemorySize, RNN_SMEM);
    cudaFuncSetAttribute(gemm_f16,   cudaFuncAttributeMaxDynamicSharedMemorySize, GF_SMEM);

    // 0) biases + fp16-split initial hidden + barrier counters
    setup_kernel<<<256, 256>>>(h0, b_ih0, b_hh0, b_ih1, b_hh1);

    // 1) P0 = x @ Wih0^T + biases   (tf32x3)
    gemm_tc<1><<<dim3(NH / 128, M_BIG / 128), 256>>>(x, W_ih0, bs0, P, M_BIG, NH, IND);

    // 2) layer-0 recurrence -> fp16 hi/lo history
    rnn_mma<1><<<NCTA, 128, RNN_SMEM>>>(P, W_hh0, h016h, h016l, H16h, H16l,
                                        nullptr, nullptr, HhA, HhB, HlA, HlB, c0);

    // 3) P1 = H0 @ Wih1^T + biases  (fp16x3 straight from the fp16 history)
    gemm_f16<<<dim3(NH / 64, M_BIG / 128), 256, GF_SMEM>>>(H16h, H16l, W_ih1, bs1, P,
                                                           M_BIG, NH, NH);

    // 4) layer-1 recurrence; final f32 state lands in h1b (t=1023 odd)
    rnn_mma<0><<<NCTA, 128, RNN_SMEM>>>(P, W_hh1, h116h, h116l, nullptr, nullptr,
                                        h1a, h1b, HhA, HhB, HlA, HlB, c1);

    // 5) head
    bn_relu<<<NH, 128>>>(h1b, bn1_g, bn1_b, y1, NH);
    gemm_bias<0><<<dim3(FC1N / 64, BB / 64), 256>>>(y1, fc1_W, fc1_b, z, BB, FC1N, NH);
    bn_relu<<<FC1N, 128>>>(z, bn2_g, bn2_b, z, FC1N);
    gemm_bias<2><<<dim3(OUTN / 64, BB / 64), 256>>>(z, fc2_W, fc2_b, out, BB, OUTN, FC1N);
}